// round 15
// baseline (speedup 1.0000x reference)
#include <cuda_runtime.h>

// MuHopf oscillator bank: B=128, D=1024, 256 steps.
// Output (float32, 33,816,576 elems): zs.real [256,128,1024], r_f, phi_f.
// R15: single-variable experiment vs R11 — plain (evict-normal, write-back)
// stores instead of __stcs streaming stores. Tests whether .cs caps the
// DRAM write drain that pins the replay period at ~26.7us.
// Math: Chebyshev cosine recurrence, 2 osc/thread, STG.64, 64-thr blocks.

#define BB 128
#define DD 1024
#define BD (BB * DD)
#define BD2 (BD / 2)
#define STEPS 256
#define ANCHOR 16
#define DT 0.01f

__global__ void __launch_bounds__(64) muhopf_kernel(
    const float2* __restrict__ x2,
    const float2* __restrict__ r2,
    const float2* __restrict__ phi2,
    const float2* __restrict__ w2,
    float2* __restrict__ out2)
{
    int t = blockIdx.x * 64 + threadIdx.x;     // 0 .. BD2-1
    if (t >= BD2) return;
    int d2 = t & (DD / 2 - 1);

    // dphi = (sigmoid(w)*4.5 + 0.5) * 2*pi * dt
    float2 wv = w2[d2];
    float sa = 1.0f / (1.0f + expf(-wv.x));
    float sb = 1.0f / (1.0f + expf(-wv.y));
    float dpa = fmaf(sa, 4.5f, 0.5f) * 6.2831855f * DT;
    float dpb = fmaf(sb, 4.5f, 0.5f) * 6.2831855f * DT;

    float2 xv = x2[t];
    float2 rv = r2[t];
    float2 pv = phi2[t];
    float mua = 5.0f * (1.0f + xv.x);
    float mub = 5.0f * (1.0f + xv.y);
    float ra = rv.x,  rb = rv.y;
    float p0a = pv.x, p0b = pv.y;

    // one-step rotation constants + Chebyshev coefficient k = 2*cos(dphi)
    float cda, sda, cdb, sdb;
    sincosf(dpa, &sda, &cda);
    sincosf(dpb, &sdb, &cdb);
    float ka = 2.0f * cda;
    float kb = 2.0f * cdb;

    float2* zs = out2 + t;

    #pragma unroll 1
    for (int s0 = 0; s0 < STEPS; s0 += ANCHOR) {
        // anchor: exact trig re-seed of the cosine recurrence
        float pha = fmaf((float)s0, dpa, p0a);
        float phb = fmaf((float)s0, dpb, p0b);
        float c0a, s0a, c0b, s0b;
        sincosf(pha, &s0a, &c0a);
        sincosf(phb, &s0b, &c0b);
        float cma = c0a, cmb = c0b;                  // cos(phi_s0)
        float ca = fmaf(c0a, cda, -s0a * sda);       // cos(phi_s0 + dphi)
        float cb = fmaf(c0b, cdb, -s0b * sdb);

        #pragma unroll
        for (int i = 0; i < ANCHOR; i++) {
            // r_{n+1} = r + (mu - r^2) * r * dt
            float ta = fmaf(-ra, ra, mua);
            float tb = fmaf(-rb, rb, mub);
            ra = fmaf(ta * ra, DT, ra);
            rb = fmaf(tb * rb, DT, rb);
            // Re(z_{n+1}) = r_{n+1} * cos(phi_{n+1}) — plain write-back store
            zs[(size_t)(s0 + i) * BD2] = make_float2(ra * ca, rb * cb);
            // Chebyshev: c_{next} = k*c - c_{prev}
            float cna = fmaf(ka, ca, -cma);
            float cnb = fmaf(kb, cb, -cmb);
            cma = ca; ca = cna;
            cmb = cb; cb = cnb;
        }
    }

    // tails: r_f then phi_f
    out2[(size_t)STEPS * BD2 + t]       = make_float2(ra, rb);
    out2[(size_t)STEPS * BD2 + BD2 + t] =
        make_float2(fmaf((float)STEPS, dpa, p0a), fmaf((float)STEPS, dpb, p0b));
}

extern "C" void kernel_launch(void* const* d_in, const int* in_sizes, int n_in,
                              void* d_out, int out_size)
{
    // ABI (confirmed R7): {x[131072], r[131072], phi[131072], omegas_raw[1024]},
    // out = 33,816,576 float32.
    const float* x   = (const float*)d_in[0];
    const float* r   = (const float*)d_in[1];
    const float* phi = (const float*)d_in[2];
    const float* w   = (const float*)d_in[3];

    // order-agnostic safety net
    {
        const float* big[3] = {0, 0, 0};
        const float* ww = 0;
        int nbig = 0;
        for (int i = 0; i < n_in; i++) {
            if (in_sizes[i] == DD) { if (!ww) ww = (const float*)d_in[i]; }
            else if (in_sizes[i] == BD && nbig < 3) big[nbig++] = (const float*)d_in[i];
        }
        if (ww && nbig == 3) { x = big[0]; r = big[1]; phi = big[2]; w = ww; }
    }

    muhopf_kernel<<<BD2 / 64, 64>>>((const float2*)x, (const float2*)r,
                                    (const float2*)phi, (const float2*)w,
                                    (float2*)d_out);
}

// round 17
// speedup vs baseline: 1.0809x; 1.0809x over previous
#include <cuda_runtime.h>

// MuHopf oscillator bank: B=128, D=1024, 256 steps.
// Output (float32, 33,816,576 elems): zs.real [256,128,1024], r_f, phi_f.
// R16: ANCHOR=32 (halved sincosf re-anchor cost; Chebyshev drift still
// ~1e-4 << 1e-3 gate), .cs streaming stores (best-measured family),
// 2 osc/thread, STG.64, 64-thread blocks.
// Model: wall is pinned by LTS double-transit (write + eviction) of the
// 135 MB output; this round discriminates gap-coupled vs drain-floor wall.

#define BB 128
#define DD 1024
#define BD (BB * DD)
#define BD2 (BD / 2)
#define STEPS 256
#define ANCHOR 32
#define DT 0.01f

__global__ void __launch_bounds__(64) muhopf_kernel(
    const float2* __restrict__ x2,
    const float2* __restrict__ r2,
    const float2* __restrict__ phi2,
    const float2* __restrict__ w2,
    float2* __restrict__ out2)
{
    int t = blockIdx.x * 64 + threadIdx.x;     // 0 .. BD2-1
    if (t >= BD2) return;
    int d2 = t & (DD / 2 - 1);

    // dphi = (sigmoid(w)*4.5 + 0.5) * 2*pi * dt
    float2 wv = w2[d2];
    float sa = 1.0f / (1.0f + expf(-wv.x));
    float sb = 1.0f / (1.0f + expf(-wv.y));
    float dpa = fmaf(sa, 4.5f, 0.5f) * 6.2831855f * DT;
    float dpb = fmaf(sb, 4.5f, 0.5f) * 6.2831855f * DT;

    float2 xv = x2[t];
    float2 rv = r2[t];
    float2 pv = phi2[t];
    float mua = 5.0f * (1.0f + xv.x);
    float mub = 5.0f * (1.0f + xv.y);
    float ra = rv.x,  rb = rv.y;
    float p0a = pv.x, p0b = pv.y;

    // one-step rotation constants + Chebyshev coefficient k = 2*cos(dphi)
    float cda, sda, cdb, sdb;
    sincosf(dpa, &sda, &cda);
    sincosf(dpb, &sdb, &cdb);
    float ka = 2.0f * cda;
    float kb = 2.0f * cdb;

    float2* zs = out2 + t;

    #pragma unroll 1
    for (int s0 = 0; s0 < STEPS; s0 += ANCHOR) {
        // anchor: exact trig re-seed of the cosine recurrence
        float pha = fmaf((float)s0, dpa, p0a);
        float phb = fmaf((float)s0, dpb, p0b);
        float c0a, s0a, c0b, s0b;
        sincosf(pha, &s0a, &c0a);
        sincosf(phb, &s0b, &c0b);
        float cma = c0a, cmb = c0b;                  // cos(phi_s0)
        float ca = fmaf(c0a, cda, -s0a * sda);       // cos(phi_s0 + dphi)
        float cb = fmaf(c0b, cdb, -s0b * sdb);

        #pragma unroll
        for (int i = 0; i < ANCHOR; i++) {
            // r_{n+1} = r + (mu - r^2) * r * dt
            float ta = fmaf(-ra, ra, mua);
            float tb = fmaf(-rb, rb, mub);
            ra = fmaf(ta * ra, DT, ra);
            rb = fmaf(tb * rb, DT, rb);
            // Re(z_{n+1}) = r_{n+1} * cos(phi_{n+1}), streamed (.cs)
            __stcs(&zs[(size_t)(s0 + i) * BD2], make_float2(ra * ca, rb * cb));
            // Chebyshev: c_{next} = k*c - c_{prev}
            float cna = fmaf(ka, ca, -cma);
            float cnb = fmaf(kb, cb, -cmb);
            cma = ca; ca = cna;
            cmb = cb; cb = cnb;
        }
    }

    // tails: r_f then phi_f
    __stcs(&out2[(size_t)STEPS * BD2 + t], make_float2(ra, rb));
    __stcs(&out2[(size_t)STEPS * BD2 + BD2 + t],
           make_float2(fmaf((float)STEPS, dpa, p0a), fmaf((float)STEPS, dpb, p0b)));
}

extern "C" void kernel_launch(void* const* d_in, const int* in_sizes, int n_in,
                              void* d_out, int out_size)
{
    // ABI (confirmed R7): {x[131072], r[131072], phi[131072], omegas_raw[1024]},
    // out = 33,816,576 float32.
    const float* x   = (const float*)d_in[0];
    const float* r   = (const float*)d_in[1];
    const float* phi = (const float*)d_in[2];
    const float* w   = (const float*)d_in[3];

    // order-agnostic safety net
    {
        const float* big[3] = {0, 0, 0};
        const float* ww = 0;
        int nbig = 0;
        for (int i = 0; i < n_in; i++) {
            if (in_sizes[i] == DD) { if (!ww) ww = (const float*)d_in[i]; }
            else if (in_sizes[i] == BD && nbig < 3) big[nbig++] = (const float*)d_in[i];
        }
        if (ww && nbig == 3) { x = big[0]; r = big[1]; phi = big[2]; w = ww; }
    }

    muhopf_kernel<<<BD2 / 64, 64>>>((const float2*)x, (const float2*)r,
                                    (const float2*)phi, (const float2*)w,
                                    (float2*)d_out);
}